// round 13
// baseline (speedup 1.0000x reference)
#include <cuda_runtime.h>
#include <cuda_fp16.h>
#include <math.h>
#include <stdint.h>

#define NTOK 8192
#define DIM  768
#define FDIM 3072
#define NEXP 8
#define NSLOT (2*NTOK)

#define BM 128
#define BN 128
#define BK 32
#define SKB 80            // smem row stride bytes (32 fp16 + 8 pad)
#define OPBUF 10240       // 128*80 per operand
#define STGBUF 20480      // A+B per stage
#define NSTAGE 4
#define SMEM_DYN (NSTAGE*STGBUF)
#define MMA_THREADS 256

// ---------------- device-global scratch ----------------
__device__ int   g_offsets[NEXP + 1];
__device__ int   g_te[NSLOT];
__device__ float g_tw[NSLOT];
__device__ int   g_perm[NSLOT];
__device__ float g_permw[NSLOT];

__device__ __align__(256) __half g_xh[(size_t)NTOK * DIM];
__device__ __align__(256) __half g_w1h[(size_t)NEXP * FDIM * DIM];
__device__ __align__(256) __half g_w2h[(size_t)NEXP * DIM * FDIM];
__device__ __align__(256) __half g_ws1h[(size_t)FDIM * DIM];
__device__ __align__(256) __half g_ws2h[(size_t)DIM * FDIM];
__device__ __align__(256) __half g_hb[(size_t)NSLOT * FDIM];
__device__ __align__(256) __half g_hsb[(size_t)NTOK * FDIM];

// ---------------- helpers ----------------
__device__ __forceinline__ uint32_t s2u(const void* p) {
    uint32_t a;
    asm("{ .reg .u64 t; cvta.to.shared.u64 t, %1; cvt.u32.u64 %0, t; }"
        : "=r"(a) : "l"(p));
    return a;
}

__device__ __forceinline__ void cp16(uint32_t dst, const void* src, bool pred) {
    int sz = pred ? 16 : 0;
    asm volatile("cp.async.cg.shared.global [%0], [%1], 16, %2;"
                 :: "r"(dst), "l"(src), "r"(sz) : "memory");
}
__device__ __forceinline__ void cp_commit() {
    asm volatile("cp.async.commit_group;" ::: "memory");
}
template <int N>
__device__ __forceinline__ void cp_wait() {
    asm volatile("cp.async.wait_group %0;" :: "n"(N) : "memory");
}

__device__ __forceinline__ void ldsm4(uint32_t (&r)[4], uint32_t addr) {
    asm volatile("ldmatrix.sync.aligned.m8n8.x4.shared.b16 {%0,%1,%2,%3}, [%4];"
                 : "=r"(r[0]), "=r"(r[1]), "=r"(r[2]), "=r"(r[3]) : "r"(addr));
}

__device__ __forceinline__ void mma16816(float (&c)[4], const uint32_t (&a)[4],
                                         uint32_t b0, uint32_t b1) {
    asm volatile(
        "mma.sync.aligned.m16n8k16.row.col.f32.f16.f16.f32 "
        "{%0,%1,%2,%3}, {%4,%5,%6,%7}, {%8,%9}, {%0,%1,%2,%3};"
        : "+f"(c[0]), "+f"(c[1]), "+f"(c[2]), "+f"(c[3])
        : "r"(a[0]), "r"(a[1]), "r"(a[2]), "r"(a[3]), "r"(b0), "r"(b1));
}

__device__ __forceinline__ float gelu_f(float v) {
    return 0.5f * v * (1.f + erff(v * 0.70710678118654752f));
}

// ---------------- small kernels ----------------

__global__ void gate_kernel(const float* __restrict__ x,
                            const float* __restrict__ gw) {
    int gid  = blockIdx.x * blockDim.x + threadIdx.x;
    int tok  = gid >> 5;
    int lane = gid & 31;
    if (tok >= NTOK) return;

    const float* xr = x + (size_t)tok * DIM;
    float xv[24];
#pragma unroll
    for (int i = 0; i < 24; i++) xv[i] = xr[lane + 32 * i];

    __half* xo = g_xh + (size_t)tok * DIM;
#pragma unroll
    for (int i = 0; i < 24; i++) xo[lane + 32 * i] = __float2half_rn(xv[i]);

    float logit[NEXP];
#pragma unroll
    for (int e = 0; e < NEXP; e++) {
        const float* w = gw + e * DIM;
        float s = 0.f;
#pragma unroll
        for (int i = 0; i < 24; i++) s = fmaf(xv[i], w[lane + 32 * i], s);
#pragma unroll
        for (int o = 16; o > 0; o >>= 1) s += __shfl_down_sync(0xffffffffu, s, o);
        logit[e] = s;
    }
    if (lane == 0) {
        int i1 = 0;
#pragma unroll
        for (int e = 1; e < NEXP; e++) if (logit[e] > logit[i1]) i1 = e;
        int i2 = (i1 == 0) ? 1 : 0;
#pragma unroll
        for (int e = 0; e < NEXP; e++) {
            if (e == i1 || e == i2) continue;
            if (logit[e] > logit[i2]) i2 = e;
        }
        float e2    = expf(logit[i2] - logit[i1]);
        float denom = 1.f + e2;
        g_te[2 * tok]     = i1;
        g_te[2 * tok + 1] = i2;
        g_tw[2 * tok]     = 1.f / denom;
        g_tw[2 * tok + 1] = e2 / denom;
    }
}

__global__ __launch_bounds__(1024)
void scatter_all_kernel() {
    __shared__ int cnt[NEXP];
    __shared__ int offs[NEXP + 1];
    __shared__ int cur[NEXP];
    const int tid = threadIdx.x;
    if (tid < NEXP) { cnt[tid] = 0; cur[tid] = 0; }
    __syncthreads();
    for (int t = tid; t < NSLOT; t += 1024)
        atomicAdd(&cnt[g_te[t]], 1);
    __syncthreads();
    if (tid == 0) {
        int s = 0;
        offs[0] = 0;
        g_offsets[0] = 0;
#pragma unroll
        for (int e = 0; e < NEXP; e++) {
            s += cnt[e];
            offs[e + 1] = s;
            g_offsets[e + 1] = s;
        }
    }
    __syncthreads();
    for (int t = tid; t < NSLOT; t += 1024) {
        int e   = g_te[t];
        int pos = offs[e] + atomicAdd(&cur[e], 1);
        g_perm[pos]  = t >> 1;
        g_permw[pos] = g_tw[t];
    }
}

#define W1_Q  ((long long)NEXP * FDIM * DIM / 4)
#define W2_Q  ((long long)NEXP * DIM * FDIM / 4)
#define WS1_Q ((long long)FDIM * DIM / 4)
#define WS2_Q ((long long)DIM * FDIM / 4)
#define CONV_TOTAL_Q (W1_Q + W2_Q + WS1_Q + WS2_Q)

__global__ void conv_all_kernel(const float* __restrict__ w1,
                                const float* __restrict__ w2,
                                const float* __restrict__ ws1,
                                const float* __restrict__ ws2) {
    long long q = (long long)blockIdx.x * blockDim.x + threadIdx.x;
    if (q >= CONV_TOTAL_Q) return;
    const float* src;
    __half* dst;
    long long base;
    if (q < W1_Q)                      { src = w1;  dst = g_w1h;  base = q; }
    else if (q < W1_Q + W2_Q)          { src = w2;  dst = g_w2h;  base = q - W1_Q; }
    else if (q < W1_Q + W2_Q + WS1_Q)  { src = ws1; dst = g_ws1h; base = q - W1_Q - W2_Q; }
    else                               { src = ws2; dst = g_ws2h; base = q - W1_Q - W2_Q - WS1_Q; }
    long long i4 = base * 4;
    float4 v = *reinterpret_cast<const float4*>(src + i4);
    __half2 a, b;
    a.x = __float2half_rn(v.x); a.y = __float2half_rn(v.y);
    b.x = __float2half_rn(v.z); b.y = __float2half_rn(v.w);
    *reinterpret_cast<__half2*>(dst + i4)     = a;
    *reinterpret_cast<__half2*>(dst + i4 + 2) = b;
}

// ---------------- mma.sync GEMM (128x128 CTA, 64x32 warp tiles) ------------
// mainloop unrolled by NSTAGE: stage addresses precomputed, no modulo.
template <int PHASE, int KD, int ND>
__global__ __launch_bounds__(MMA_THREADS, 2)
void mma_kernel(const __half* __restrict__ Ar, const __half* __restrict__ Ash,
                const __half* __restrict__ Br, const __half* __restrict__ Bsh,
                const float* __restrict__ biasR, const float* __restrict__ biasS,
                float* __restrict__ outp) {
    const int e = blockIdx.z;              // 0..7 routed, 8 = shared expert
    const bool se = (e == NEXP);
    int seg_start = 0, seg_len = NTOK;
    if (!se) {
        seg_start = g_offsets[e];
        seg_len   = g_offsets[e + 1] - seg_start;
    }
    const int m0 = blockIdx.y * BM;
    if (m0 >= seg_len) return;
    const int n0 = blockIdx.x * BN;

    extern __shared__ __align__(128) char smem[];
    const uint32_t sbase = s2u(smem);

    const int tid  = threadIdx.x;
    const int wid  = tid >> 5;
    const int lane = tid & 31;
    const int wm   = wid >> 2;
    const int wn   = wid & 3;

    // gmem pointers for cp.async
    const int lr = tid >> 2;     // 0..63
    const int cc = tid & 3;      // 8-halfword chunk
    const __half* aptr[2];
    bool av[2];
#pragma unroll
    for (int h = 0; h < 2; h++) {
        int gr = m0 + lr + h * 64;
        bool v = (gr < seg_len);
        const __half* p;
        if (se) {
            p = Ash + (size_t)(v ? gr : 0) * KD;
        } else if (PHASE == 1) {
            int tok = v ? g_perm[seg_start + gr] : 0;
            p = Ar + (size_t)tok * KD;
        } else {
            p = Ar + (size_t)(seg_start + (v ? gr : 0)) * KD;
        }
        aptr[h] = p + cc * 8;
        av[h]   = v;
    }
    const __half* bptr[2];
#pragma unroll
    for (int h = 0; h < 2; h++) {
        int brow = n0 + lr + h * 64;
        bptr[h] = (se ? Bsh + (size_t)brow * KD
                      : Br + ((size_t)e * ND + brow) * KD) + cc * 8;
    }

    const uint32_t sdst = (uint32_t)(lr * SKB + cc * 16);

    auto load_tile = [&](int kt, int buf) {
        const int k0 = kt * BK;
        uint32_t da = sbase + buf * STGBUF + sdst;
        uint32_t db = da + OPBUF;
        cp16(da,            aptr[0] + k0, av[0]);
        cp16(da + 64 * SKB, aptr[1] + k0, av[1]);
        cp16(db,            bptr[0] + k0, true);
        cp16(db + 64 * SKB, bptr[1] + k0, true);
    };

    const uint32_t aoff = (uint32_t)((wm * 64 + (lane & 15)) * SKB + (lane >> 4) * 16);
    const uint32_t boff = (uint32_t)((wn * 32 + (lane & 15)) * SKB + (lane >> 4) * 16)
                          + OPBUF;

    // precomputed per-stage smem read bases (compile-time stage indexing below)
    uint32_t abS[NSTAGE], bbS[NSTAGE];
#pragma unroll
    for (int s = 0; s < NSTAGE; s++) {
        abS[s] = sbase + s * STGBUF + aoff;
        bbS[s] = sbase + s * STGBUF + boff;
    }

    float acc[4][4][4];
#pragma unroll
    for (int i = 0; i < 4; i++)
#pragma unroll
        for (int j = 0; j < 4; j++)
#pragma unroll
            for (int q = 0; q < 4; q++) acc[i][j][q] = 0.f;

    constexpr int nt = KD / BK;            // 24 (fc1) or 96 (fc2); % NSTAGE == 0
    static_assert(nt % NSTAGE == 0, "nt must be multiple of NSTAGE");
    load_tile(0, 0); cp_commit();
    load_tile(1, 1); cp_commit();
    load_tile(2, 2); cp_commit();

#pragma unroll 1
    for (int t0 = 0; t0 < nt; t0 += NSTAGE) {
#pragma unroll
        for (int s = 0; s < NSTAGE; s++) {
            const int t = t0 + s;
            cp_wait<2>();
            __syncthreads();

            const uint32_t ab = abS[s];
            const uint32_t bb = bbS[s];
#pragma unroll
            for (int ks = 0; ks < 2; ks++) {
                uint32_t br[2][4];
                ldsm4(br[0], bb + ks * 32);
                ldsm4(br[1], bb + 1280 + ks * 32);
#pragma unroll
                for (int i = 0; i < 4; i++) {
                    uint32_t ar[4];
                    ldsm4(ar, ab + i * 1280 + ks * 32);
#pragma unroll
                    for (int jn = 0; jn < 4; jn++) {
                        int jp = jn >> 1, sub = jn & 1;
                        mma16816(acc[i][jn], ar, br[jp][sub], br[jp][sub + 2]);
                    }
                }
            }
            if (t + 3 < nt) load_tile(t + 3, (s + 3) & (NSTAGE - 1));
            cp_commit();
        }
    }

    // ---- epilogue ----
    const float* bias = se ? biasS : biasR + (size_t)e * ND;
    const int colb = wn * 32 + (lane & 3) * 2;
#pragma unroll
    for (int i = 0; i < 4; i++) {
#pragma unroll
        for (int half = 0; half < 2; half++) {
            const int rl = wm * 64 + i * 16 + (lane >> 2) + half * 8;
            const int gr = m0 + rl;
            if (gr >= seg_len) continue;
            float wgt = 1.f;
            if (PHASE == 2 && !se) wgt = g_permw[seg_start + gr];
            int tokr = 0;
            if (PHASE == 2) tokr = se ? gr : g_perm[seg_start + gr];
#pragma unroll
            for (int jn = 0; jn < 4; jn++) {
                const int c = n0 + colb + jn * 8;
                float v0 = acc[i][jn][2 * half]     + bias[c];
                float v1 = acc[i][jn][2 * half + 1] + bias[c + 1];
                if (PHASE == 1) {
                    v0 = gelu_f(v0); v1 = gelu_f(v1);
                    __half2 hp;
                    hp.x = __float2half_rn(v0);
                    hp.y = __float2half_rn(v1);
                    __half* hout = se ? g_hsb : g_hb;
                    size_t base = se ? (size_t)gr * FDIM
                                     : (size_t)(seg_start + gr) * FDIM;
                    *reinterpret_cast<__half2*>(hout + base + c) = hp;
                } else {
                    float* op = outp + (size_t)tokr * DIM + c;
                    atomicAdd(op,     wgt * v0);
                    atomicAdd(op + 1, wgt * v1);
                }
            }
        }
    }
}

// ---------------- launch ----------------
extern "C" void kernel_launch(void* const* d_in, const int* in_sizes, int n_in,
                              void* d_out, int out_size) {
    const float* x   = (const float*)d_in[0];
    const float* gw  = (const float*)d_in[1];
    const float* w1  = (const float*)d_in[2];
    const float* b1  = (const float*)d_in[3];
    const float* w2  = (const float*)d_in[4];
    const float* b2  = (const float*)d_in[5];
    const float* ws1 = (const float*)d_in[6];
    const float* bs1 = (const float*)d_in[7];
    const float* ws2 = (const float*)d_in[8];
    const float* bs2 = (const float*)d_in[9];
    float* out = (float*)d_out;

    void *pxh, *pw1h, *pw2h, *pws1h, *pws2h, *phb, *phsb;
    cudaGetSymbolAddress(&pxh,   g_xh);
    cudaGetSymbolAddress(&pw1h,  g_w1h);
    cudaGetSymbolAddress(&pw2h,  g_w2h);
    cudaGetSymbolAddress(&pws1h, g_ws1h);
    cudaGetSymbolAddress(&pws2h, g_ws2h);
    cudaGetSymbolAddress(&phb,   g_hb);
    cudaGetSymbolAddress(&phsb,  g_hsb);

    cudaFuncSetAttribute(mma_kernel<1, DIM, FDIM>,
                         cudaFuncAttributeMaxDynamicSharedMemorySize, SMEM_DYN);
    cudaFuncSetAttribute(mma_kernel<2, FDIM, DIM>,
                         cudaFuncAttributeMaxDynamicSharedMemorySize, SMEM_DYN);

    // zero-fill output (fc2 accumulates into it atomically)
    cudaMemsetAsync(out, 0, (size_t)out_size * sizeof(float));

    gate_kernel<<<(NTOK * 32 + 255) / 256, 256>>>(x, gw);
    scatter_all_kernel<<<1, 1024>>>();
    conv_all_kernel<<<(unsigned)((CONV_TOTAL_Q + 255) / 256), 256>>>(
        w1, w2, ws1, ws2);

    // fc1: z = 0..7 routed experts, z = 8 shared expert
    mma_kernel<1, DIM, FDIM>
        <<<dim3(FDIM / BN, NSLOT / BM, NEXP + 1), MMA_THREADS, SMEM_DYN>>>(
            (const __half*)pxh, (const __half*)pxh,
            (const __half*)pw1h, (const __half*)pws1h, b1, bs1, nullptr);
    // fc2: accumulates directly into out
    mma_kernel<2, FDIM, DIM>
        <<<dim3(DIM / BN, NSLOT / BM, NEXP + 1), MMA_THREADS, SMEM_DYN>>>(
            (const __half*)phb, (const __half*)phsb,
            (const __half*)pw2h, (const __half*)pws2h, b2, bs2, out);
}

// round 16
// speedup vs baseline: 1.0641x; 1.0641x over previous
#include <cuda_runtime.h>
#include <cuda_fp16.h>
#include <math.h>
#include <stdint.h>

#define NTOK 8192
#define DIM  768
#define FDIM 3072
#define NEXP 8
#define NSLOT (2*NTOK)

#define BM 128
#define BN 128
#define BK 32
#define SKB 80            // smem row stride bytes (32 fp16 + 8 pad)
#define OPBUF 10240       // 128*80 per operand
#define STGBUF 20480      // A+B per stage
#define NSTAGE 4
#define SMEM_DYN (NSTAGE*STGBUF)
#define MMA_THREADS 256

// max tiles: sum_e ceil(seg_e/BM) <= 16384/128 + 8 = 136, + shared 64 = 200
#define MAXTILE 200
#define TM_PAD 0xFFFF0000u

// ---------------- device-global scratch ----------------
__device__ int      g_offsets[NEXP + 1];
__device__ int      g_te[NSLOT];
__device__ float    g_tw[NSLOT];
__device__ int      g_perm[NSLOT];
__device__ float    g_permw[NSLOT];
__device__ unsigned g_tmap[MAXTILE];   // (expert<<16)|yblock ; TM_PAD = empty

__device__ __align__(256) __half g_xh[(size_t)NTOK * DIM];
__device__ __align__(256) __half g_w1h[(size_t)NEXP * FDIM * DIM];
__device__ __align__(256) __half g_w2h[(size_t)NEXP * DIM * FDIM];
__device__ __align__(256) __half g_ws1h[(size_t)FDIM * DIM];
__device__ __align__(256) __half g_ws2h[(size_t)DIM * FDIM];
__device__ __align__(256) __half g_hb[(size_t)NSLOT * FDIM];
__device__ __align__(256) __half g_hsb[(size_t)NTOK * FDIM];

// ---------------- helpers ----------------
__device__ __forceinline__ uint32_t s2u(const void* p) {
    uint32_t a;
    asm("{ .reg .u64 t; cvta.to.shared.u64 t, %1; cvt.u32.u64 %0, t; }"
        : "=r"(a) : "l"(p));
    return a;
}

__device__ __forceinline__ void cp16(uint32_t dst, const void* src, bool pred) {
    int sz = pred ? 16 : 0;
    asm volatile("cp.async.cg.shared.global [%0], [%1], 16, %2;"
                 :: "r"(dst), "l"(src), "r"(sz) : "memory");
}
__device__ __forceinline__ void cp_commit() {
    asm volatile("cp.async.commit_group;" ::: "memory");
}
template <int N>
__device__ __forceinline__ void cp_wait() {
    asm volatile("cp.async.wait_group %0;" :: "n"(N) : "memory");
}

__device__ __forceinline__ void ldsm4(uint32_t (&r)[4], uint32_t addr) {
    asm volatile("ldmatrix.sync.aligned.m8n8.x4.shared.b16 {%0,%1,%2,%3}, [%4];"
                 : "=r"(r[0]), "=r"(r[1]), "=r"(r[2]), "=r"(r[3]) : "r"(addr));
}

__device__ __forceinline__ void mma16816(float (&c)[4], const uint32_t (&a)[4],
                                         uint32_t b0, uint32_t b1) {
    asm volatile(
        "mma.sync.aligned.m16n8k16.row.col.f32.f16.f16.f32 "
        "{%0,%1,%2,%3}, {%4,%5,%6,%7}, {%8,%9}, {%0,%1,%2,%3};"
        : "+f"(c[0]), "+f"(c[1]), "+f"(c[2]), "+f"(c[3])
        : "r"(a[0]), "r"(a[1]), "r"(a[2]), "r"(a[3]), "r"(b0), "r"(b1));
}

__device__ __forceinline__ float gelu_f(float v) {
    return 0.5f * v * (1.f + erff(v * 0.70710678118654752f));
}

// ---------------- small kernels ----------------

__global__ void gate_kernel(const float* __restrict__ x,
                            const float* __restrict__ gw) {
    int gid  = blockIdx.x * blockDim.x + threadIdx.x;
    int tok  = gid >> 5;
    int lane = gid & 31;
    if (tok >= NTOK) return;

    const float* xr = x + (size_t)tok * DIM;
    float xv[24];
#pragma unroll
    for (int i = 0; i < 24; i++) xv[i] = xr[lane + 32 * i];

    __half* xo = g_xh + (size_t)tok * DIM;
#pragma unroll
    for (int i = 0; i < 24; i++) xo[lane + 32 * i] = __float2half_rn(xv[i]);

    float logit[NEXP];
#pragma unroll
    for (int e = 0; e < NEXP; e++) {
        const float* w = gw + e * DIM;
        float s = 0.f;
#pragma unroll
        for (int i = 0; i < 24; i++) s = fmaf(xv[i], w[lane + 32 * i], s);
#pragma unroll
        for (int o = 16; o > 0; o >>= 1) s += __shfl_down_sync(0xffffffffu, s, o);
        logit[e] = s;
    }
    if (lane == 0) {
        int i1 = 0;
#pragma unroll
        for (int e = 1; e < NEXP; e++) if (logit[e] > logit[i1]) i1 = e;
        int i2 = (i1 == 0) ? 1 : 0;
#pragma unroll
        for (int e = 0; e < NEXP; e++) {
            if (e == i1 || e == i2) continue;
            if (logit[e] > logit[i2]) i2 = e;
        }
        float e2    = expf(logit[i2] - logit[i1]);
        float denom = 1.f + e2;
        g_te[2 * tok]     = i1;
        g_te[2 * tok + 1] = i2;
        g_tw[2 * tok]     = 1.f / denom;
        g_tw[2 * tok + 1] = e2 / denom;
    }
}

// single block: count, prefix, scatter, AND build compact tile map.
__global__ __launch_bounds__(1024)
void scatter_all_kernel() {
    __shared__ int cnt[NEXP];
    __shared__ int offs[NEXP + 1];
    __shared__ int cur[NEXP];
    const int tid = threadIdx.x;
    if (tid < NEXP) { cnt[tid] = 0; cur[tid] = 0; }
    __syncthreads();
    for (int t = tid; t < NSLOT; t += 1024)
        atomicAdd(&cnt[g_te[t]], 1);
    __syncthreads();
    if (tid == 0) {
        int s = 0;
        offs[0] = 0;
        g_offsets[0] = 0;
#pragma unroll
        for (int e = 0; e < NEXP; e++) {
            s += cnt[e];
            offs[e + 1] = s;
            g_offsets[e + 1] = s;
        }
        // compact tile map: routed experts then shared (e = NEXP)
        int idx = 0;
#pragma unroll
        for (int e = 0; e < NEXP; e++) {
            int nb = (cnt[e] + BM - 1) / BM;
            for (int yb = 0; yb < nb; yb++)
                g_tmap[idx++] = ((unsigned)e << 16) | (unsigned)yb;
        }
        for (int yb = 0; yb < NTOK / BM; yb++)
            g_tmap[idx++] = ((unsigned)NEXP << 16) | (unsigned)yb;
        for (; idx < MAXTILE; idx++)
            g_tmap[idx] = TM_PAD;
    }
    __syncthreads();
    for (int t = tid; t < NSLOT; t += 1024) {
        int e   = g_te[t];
        int pos = offs[e] + atomicAdd(&cur[e], 1);
        g_perm[pos]  = t >> 1;
        g_permw[pos] = g_tw[t];
    }
}

#define W1_Q  ((long long)NEXP * FDIM * DIM / 4)
#define W2_Q  ((long long)NEXP * DIM * FDIM / 4)
#define WS1_Q ((long long)FDIM * DIM / 4)
#define WS2_Q ((long long)DIM * FDIM / 4)
#define CONV_TOTAL_Q (W1_Q + W2_Q + WS1_Q + WS2_Q)

__global__ void conv_all_kernel(const float* __restrict__ w1,
                                const float* __restrict__ w2,
                                const float* __restrict__ ws1,
                                const float* __restrict__ ws2) {
    long long q = (long long)blockIdx.x * blockDim.x + threadIdx.x;
    if (q >= CONV_TOTAL_Q) return;
    const float* src;
    __half* dst;
    long long base;
    if (q < W1_Q)                      { src = w1;  dst = g_w1h;  base = q; }
    else if (q < W1_Q + W2_Q)          { src = w2;  dst = g_w2h;  base = q - W1_Q; }
    else if (q < W1_Q + W2_Q + WS1_Q)  { src = ws1; dst = g_ws1h; base = q - W1_Q - W2_Q; }
    else                               { src = ws2; dst = g_ws2h; base = q - W1_Q - W2_Q - WS1_Q; }
    long long i4 = base * 4;
    float4 v = *reinterpret_cast<const float4*>(src + i4);
    __half2 a, b;
    a.x = __float2half_rn(v.x); a.y = __float2half_rn(v.y);
    b.x = __float2half_rn(v.z); b.y = __float2half_rn(v.w);
    *reinterpret_cast<__half2*>(dst + i4)     = a;
    *reinterpret_cast<__half2*>(dst + i4 + 2) = b;
}

// ---------------- mma.sync GEMM (R12 mainloop + compact tile map) ----------
// blockIdx.y indexes g_tmap -> (expert, y-block). e==0xFFFF -> empty pad tile.
template <int PHASE, int KD, int ND>
__global__ __launch_bounds__(MMA_THREADS, 2)
void mma_kernel(const __half* __restrict__ Ar, const __half* __restrict__ Ash,
                const __half* __restrict__ Br, const __half* __restrict__ Bsh,
                const float* __restrict__ biasR, const float* __restrict__ biasS,
                float* __restrict__ outp) {
    const unsigned tm = g_tmap[blockIdx.y];
    const unsigned eu = tm >> 16;          // unsigned: pad -> 0xFFFF
    if (eu >= 0xFFFFu || eu > (unsigned)NEXP) return;   // pad tile
    const int e  = (int)eu;
    const bool se = (e == NEXP);
    int seg_start = 0, seg_len = NTOK;
    if (!se) {
        seg_start = g_offsets[e];
        seg_len   = g_offsets[e + 1] - seg_start;
    }
    const int m0 = (int)(tm & 0xFFFFu) * BM;
    if (m0 >= seg_len) return;
    const int n0 = blockIdx.x * BN;

    extern __shared__ __align__(128) char smem[];
    const uint32_t sbase = s2u(smem);

    const int tid  = threadIdx.x;
    const int wid  = tid >> 5;
    const int lane = tid & 31;
    const int wm   = wid >> 2;
    const int wn   = wid & 3;

    // gmem pointers for cp.async
    const int lr = tid >> 2;     // 0..63
    const int cc = tid & 3;      // 8-halfword chunk
    const __half* aptr[2];
    bool av[2];
#pragma unroll
    for (int h = 0; h < 2; h++) {
        int gr = m0 + lr + h * 64;
        bool v = (gr < seg_len);
        const __half* p;
        if (se) {
            p = Ash + (size_t)(v ? gr : 0) * KD;
        } else if (PHASE == 1) {
            int tok = v ? g_perm[seg_start + gr] : 0;
            p = Ar + (size_t)tok * KD;
        } else {
            p = Ar + (size_t)(seg_start + (v ? gr : 0)) * KD;
        }
        aptr[h] = p + cc * 8;
        av[h]   = v;
    }
    const __half* bptr[2];
#pragma unroll
    for (int h = 0; h < 2; h++) {
        int brow = n0 + lr + h * 64;
        bptr[h] = (se ? Bsh + (size_t)brow * KD
                      : Br + ((size_t)e * ND + brow) * KD) + cc * 8;
    }

    const uint32_t sdst = (uint32_t)(lr * SKB + cc * 16);

    auto load_tile = [&](int kt, int buf) {
        const int k0 = kt * BK;
        uint32_t da = sbase + buf * STGBUF + sdst;
        uint32_t db = da + OPBUF;
        cp16(da,            aptr[0] + k0, av[0]);
        cp16(da + 64 * SKB, aptr[1] + k0, av[1]);
        cp16(db,            bptr[0] + k0, true);
        cp16(db + 64 * SKB, bptr[1] + k0, true);
    };

    const uint32_t aoff = (uint32_t)((wm * 64 + (lane & 15)) * SKB + (lane >> 4) * 16);
    const uint32_t boff = (uint32_t)((wn * 32 + (lane & 15)) * SKB + (lane >> 4) * 16)
                          + OPBUF;

    float acc[4][4][4];
#pragma unroll
    for (int i = 0; i < 4; i++)
#pragma unroll
        for (int j = 0; j < 4; j++)
#pragma unroll
            for (int q = 0; q < 4; q++) acc[i][j][q] = 0.f;

    const int nt = KD / BK;
    load_tile(0, 0); cp_commit();
    load_tile(1, 1); cp_commit();
    load_tile(2, 2); cp_commit();

    int buf = 0;
    for (int t = 0; t < nt; t++) {
        cp_wait<2>();
        __syncthreads();

        const uint32_t ab = sbase + buf * STGBUF + aoff;
        const uint32_t bb = sbase + buf * STGBUF + boff;
#pragma unroll
        for (int ks = 0; ks < 2; ks++) {
            uint32_t br[2][4];
            ldsm4(br[0], bb + ks * 32);
            ldsm4(br[1], bb + 1280 + ks * 32);
#pragma unroll
            for (int i = 0; i < 4; i++) {
                uint32_t ar[4];
                ldsm4(ar, ab + i * 1280 + ks * 32);
#pragma unroll
                for (int jn = 0; jn < 4; jn++) {
                    int jp = jn >> 1, sub = jn & 1;
                    mma16816(acc[i][jn], ar, br[jp][sub], br[jp][sub + 2]);
                }
            }
        }
        if (t + 3 < nt) load_tile(t + 3, (t + 3) % NSTAGE);
        cp_commit();
        buf = (buf + 1 == NSTAGE) ? 0 : buf + 1;
    }

    // ---- epilogue ----
    const float* bias = se ? biasS : biasR + (size_t)e * ND;
    const int colb = wn * 32 + (lane & 3) * 2;
#pragma unroll
    for (int i = 0; i < 4; i++) {
#pragma unroll
        for (int half = 0; half < 2; half++) {
            const int rl = wm * 64 + i * 16 + (lane >> 2) + half * 8;
            const int gr = m0 + rl;
            if (gr >= seg_len) continue;
            float wgt = 1.f;
            if (PHASE == 2 && !se) wgt = g_permw[seg_start + gr];
            int tokr = 0;
            if (PHASE == 2) tokr = se ? gr : g_perm[seg_start + gr];
#pragma unroll
            for (int jn = 0; jn < 4; jn++) {
                const int c = n0 + colb + jn * 8;
                float v0 = acc[i][jn][2 * half]     + bias[c];
                float v1 = acc[i][jn][2 * half + 1] + bias[c + 1];
                if (PHASE == 1) {
                    v0 = gelu_f(v0); v1 = gelu_f(v1);
                    __half2 hp;
                    hp.x = __float2half_rn(v0);
                    hp.y = __float2half_rn(v1);
                    __half* hout = se ? g_hsb : g_hb;
                    size_t base = se ? (size_t)gr * FDIM
                                     : (size_t)(seg_start + gr) * FDIM;
                    *reinterpret_cast<__half2*>(hout + base + c) = hp;
                } else {
                    float* op = outp + (size_t)tokr * DIM + c;
                    atomicAdd(op,     wgt * v0);
                    atomicAdd(op + 1, wgt * v1);
                }
            }
        }
    }
}

// ---------------- launch ----------------
extern "C" void kernel_launch(void* const* d_in, const int* in_sizes, int n_in,
                              void* d_out, int out_size) {
    const float* x   = (const float*)d_in[0];
    const float* gw  = (const float*)d_in[1];
    const float* w1  = (const float*)d_in[2];
    const float* b1  = (const float*)d_in[3];
    const float* w2  = (const float*)d_in[4];
    const float* b2  = (const float*)d_in[5];
    const float* ws1 = (const float*)d_in[6];
    const float* bs1 = (const float*)d_in[7];
    const float* ws2 = (const float*)d_in[8];
    const float* bs2 = (const float*)d_in[9];
    float* out = (float*)d_out;

    void *pxh, *pw1h, *pw2h, *pws1h, *pws2h, *phb, *phsb;
    cudaGetSymbolAddress(&pxh,   g_xh);
    cudaGetSymbolAddress(&pw1h,  g_w1h);
    cudaGetSymbolAddress(&pw2h,  g_w2h);
    cudaGetSymbolAddress(&pws1h, g_ws1h);
    cudaGetSymbolAddress(&pws2h, g_ws2h);
    cudaGetSymbolAddress(&phb,   g_hb);
    cudaGetSymbolAddress(&phsb,  g_hsb);

    cudaFuncSetAttribute(mma_kernel<1, DIM, FDIM>,
                         cudaFuncAttributeMaxDynamicSharedMemorySize, SMEM_DYN);
    cudaFuncSetAttribute(mma_kernel<2, FDIM, DIM>,
                         cudaFuncAttributeMaxDynamicSharedMemorySize, SMEM_DYN);

    // zero-fill output (fc2 accumulates into it atomically)
    cudaMemsetAsync(out, 0, (size_t)out_size * sizeof(float));

    gate_kernel<<<(NTOK * 32 + 255) / 256, 256>>>(x, gw);
    scatter_all_kernel<<<1, 1024>>>();
    conv_all_kernel<<<(unsigned)((CONV_TOTAL_Q + 255) / 256), 256>>>(
        w1, w2, ws1, ws2);

    // fc1: compact tile grid (x = N-blocks, y = tile map)
    mma_kernel<1, DIM, FDIM>
        <<<dim3(FDIM / BN, MAXTILE, 1), MMA_THREADS, SMEM_DYN>>>(
            (const __half*)pxh, (const __half*)pxh,
            (const __half*)pw1h, (const __half*)pws1h, b1, bs1, nullptr);
    // fc2: accumulates directly into out
    mma_kernel<2, FDIM, DIM>
        <<<dim3(DIM / BN, MAXTILE, 1), MMA_THREADS, SMEM_DYN>>>(
            (const __half*)phb, (const __half*)phsb,
            (const __half*)pw2h, (const __half*)pws2h, b2, bs2, out);
}